// round 1
// baseline (speedup 1.0000x reference)
#include <cuda_runtime.h>

// LSTM autoencoder: T=1024, B=1024, IN=1, H=64
//   encoder: 1024 sequential steps of [B,64]@[64,256] + LSTM cell
//   decoder: hidden=1, input = h_enc constant -> precompute z, scalar recurrence
//
// Encoder: 128 blocks x 256 threads, 8 batch rows per block.
//   thread = one gate column g in [0,256); holds its 65 weights in registers
//   (64 Whh + 1 Wih "extended" row for x), accumulates 8 batch rows as 4
//   packed f32x2 pairs. h kept in shared [k][b] (row stride 12 floats for
//   16B alignment + reduced STS conflicts). Two barriers per step.

#define T_STEPS 1024
#define BATCH   1024
#define HID     64
#define GATES   256
#define BB      8          // batch rows per block
#define HROW    12         // padded row stride (floats) for h_s

__device__ float g_henc[HID * BATCH];   // h_enc transposed: [k][b]

__device__ __forceinline__ unsigned long long pk2(float a, float b) {
    unsigned long long r;
    asm("mov.b64 %0, {%1,%2};" : "=l"(r) : "f"(a), "f"(b));
    return r;
}
__device__ __forceinline__ unsigned long long fma2(unsigned long long a,
                                                   unsigned long long b,
                                                   unsigned long long c) {
    unsigned long long d;
    asm("fma.rn.f32x2 %0, %1, %2, %3;" : "=l"(d) : "l"(a), "l"(b), "l"(c));
    return d;
}
__device__ __forceinline__ void upk(unsigned long long v, float& lo, float& hi) {
    asm("mov.b64 {%0,%1}, %2;" : "=f"(lo), "=f"(hi) : "l"(v));
}
__device__ __forceinline__ float sigf(float x) {
    return __fdividef(1.0f, 1.0f + __expf(-x));
}
__device__ __forceinline__ float tanhf_(float x) {
    // tanh(x) = 2*sigmoid(2x) - 1
    return 2.0f * __fdividef(1.0f, 1.0f + __expf(-2.0f * x)) - 1.0f;
}

__global__ void __launch_bounds__(256, 1)
enc_kernel(const float* __restrict__ x,
           const float* __restrict__ Wih,
           const float* __restrict__ Whh,
           const float* __restrict__ bih,
           const float* __restrict__ bhh)
{
    __shared__ __align__(16) float h_s[65 * HROW];   // [k][b], k=64 row holds x_t
    __shared__ float gbuf[BB * GATES];               // gate exchange [b][g]

    const int tid   = threadIdx.x;
    const int bbase = blockIdx.x * BB;
    const int g     = tid;

    // ---- preload time-invariant weights into registers ----
    float Wr[65];
#pragma unroll
    for (int k = 0; k < 64; k++) Wr[k] = Whh[g * 64 + k];
    Wr[64] = Wih[g];                       // x contribution (IN = 1)
    const float bias = bih[g] + bhh[g];
    const unsigned long long bias2 = pk2(bias, bias);

    // ---- zero h state ----
    for (int i = tid; i < 65 * HROW; i += 256) h_s[i] = 0.0f;

    const int j  = tid & 63;     // epilogue cell index
    const int bp = tid >> 6;     // epilogue batch-pair (0..3)
    float c0 = 0.0f, c1 = 0.0f;  // cell state for rows 2*bp, 2*bp+1

    __syncthreads();

    for (int t = 0; t < T_STEPS; t++) {
        // stage x_t into the extended k=64 row (disjoint from epilogue rows)
        if (tid < BB) h_s[64 * HROW + tid] = x[t * BATCH + bbase + tid];
        __syncthreads();   // orders prev epilogue h writes + x before reads

        // ---- gates[b][g] = sum_k h[k][b] * Wr[k]  (packed over batch pairs)
        unsigned long long a0 = bias2, a1 = bias2, a2 = bias2, a3 = bias2;
#pragma unroll
        for (int k = 0; k < 65; k++) {
            const ulonglong2 hA = *(const ulonglong2*)(h_s + k * HROW);     // b0..3
            const ulonglong2 hB = *(const ulonglong2*)(h_s + k * HROW + 4); // b4..7
            const unsigned long long w2 = pk2(Wr[k], Wr[k]);
            a0 = fma2(hA.x, w2, a0);
            a1 = fma2(hA.y, w2, a1);
            a2 = fma2(hB.x, w2, a2);
            a3 = fma2(hB.y, w2, a3);
        }

        float v0, v1, v2, v3, v4, v5, v6, v7;
        upk(a0, v0, v1); upk(a1, v2, v3); upk(a2, v4, v5); upk(a3, v6, v7);
        gbuf[0 * GATES + g] = v0;
        gbuf[1 * GATES + g] = v1;
        gbuf[2 * GATES + g] = v2;
        gbuf[3 * GATES + g] = v3;
        gbuf[4 * GATES + g] = v4;
        gbuf[5 * GATES + g] = v5;
        gbuf[6 * GATES + g] = v6;
        gbuf[7 * GATES + g] = v7;
        __syncthreads();

        // ---- LSTM cell epilogue: thread handles cell j for 2 batch rows ----
        {
            const int b0 = 2 * bp, b1 = 2 * bp + 1;
            const float* gb0 = gbuf + b0 * GATES;
            const float* gb1 = gbuf + b1 * GATES;

            float i0 = sigf(gb0[j]);
            float f0 = sigf(gb0[64 + j]);
            float G0 = tanhf_(gb0[128 + j]);
            float o0 = sigf(gb0[192 + j]);
            c0 = f0 * c0 + i0 * G0;
            h_s[j * HROW + b0] = o0 * tanhf_(c0);

            float i1 = sigf(gb1[j]);
            float f1 = sigf(gb1[64 + j]);
            float G1 = tanhf_(gb1[128 + j]);
            float o1 = sigf(gb1[192 + j]);
            c1 = f1 * c1 + i1 * G1;
            h_s[j * HROW + b1] = o1 * tanhf_(c1);
        }
        // next iteration's x-store + barrier provide the ordering
    }

    __syncthreads();
    // ---- export final h (transposed [k][b]) for the decoder ----
    for (int idx = tid; idx < HID * BB; idx += 256) {
        const int k = idx >> 3;
        const int b = idx & 7;
        g_henc[k * BATCH + bbase + b] = h_s[k * HROW + b];
    }
}

__global__ void __launch_bounds__(64)
dec_kernel(const float* __restrict__ Wih,
           const float* __restrict__ Whh,
           const float* __restrict__ bih,
           const float* __restrict__ bhh,
           float* __restrict__ out)
{
    const int b = blockIdx.x * 64 + threadIdx.x;

    // z[g] = h_enc[b] . Wih_d[g] + bias  (constant across all decoder steps)
    float z0 = bih[0] + bhh[0];
    float z1 = bih[1] + bhh[1];
    float z2 = bih[2] + bhh[2];
    float z3 = bih[3] + bhh[3];
#pragma unroll 8
    for (int k = 0; k < HID; k++) {
        const float hv = g_henc[k * BATCH + b];   // coalesced
        z0 = fmaf(hv, Wih[0 * HID + k], z0);
        z1 = fmaf(hv, Wih[1 * HID + k], z1);
        z2 = fmaf(hv, Wih[2 * HID + k], z2);
        z3 = fmaf(hv, Wih[3 * HID + k], z3);
    }
    const float w0 = Whh[0], w1 = Whh[1], w2 = Whh[2], w3 = Whh[3];

    float h = 0.0f, c = 0.0f;
    for (int t = 0; t < T_STEPS; t++) {
        const float i = sigf(z0 + h * w0);
        const float f = sigf(z1 + h * w1);
        const float G = tanhf_(z2 + h * w2);
        const float o = sigf(z3 + h * w3);
        c = f * c + i * G;
        h = o * tanhf_(c);
        out[t * BATCH + b] = h;   // coalesced
    }
}

extern "C" void kernel_launch(void* const* d_in, const int* in_sizes, int n_in,
                              void* d_out, int out_size)
{
    const float* x     = (const float*)d_in[0];
    const float* Wih_e = (const float*)d_in[1];
    const float* Whh_e = (const float*)d_in[2];
    const float* bih_e = (const float*)d_in[3];
    const float* bhh_e = (const float*)d_in[4];
    const float* Wih_d = (const float*)d_in[5];
    const float* Whh_d = (const float*)d_in[6];
    const float* bih_d = (const float*)d_in[7];
    const float* bhh_d = (const float*)d_in[8];

    enc_kernel<<<BATCH / BB, 256>>>(x, Wih_e, Whh_e, bih_e, bhh_e);
    dec_kernel<<<BATCH / 64, 64>>>(Wih_d, Whh_d, bih_d, bhh_d, (float*)d_out);
}

// round 2
// speedup vs baseline: 1.2492x; 1.2492x over previous
#include <cuda_runtime.h>

// LSTM autoencoder: T=1024, B=1024, IN=1, H=64
// Encoder: 256 blocks x 256 threads, BB=4 batch rows/block, 2 blocks/SM.
//   thread = gate column g in [0,256); 65 scalar weights in regs; 2 packed
//   f32x2 accumulators over the 4 batch rows; x[t+1] prefetched.
// Epilogue + decoder use MUFU.TANH (tanh.approx.f32), 1 MUFU per activation.

#define T_STEPS 1024
#define BATCH   1024
#define HID     64
#define GATES   256
#define BB      4          // batch rows per block

__device__ float g_henc[HID * BATCH];   // h_enc transposed: [k][b]

__device__ __forceinline__ unsigned long long pk2(float a, float b) {
    unsigned long long r;
    asm("mov.b64 %0, {%1,%2};" : "=l"(r) : "f"(a), "f"(b));
    return r;
}
__device__ __forceinline__ unsigned long long fma2(unsigned long long a,
                                                   unsigned long long b,
                                                   unsigned long long c) {
    unsigned long long d;
    asm("fma.rn.f32x2 %0, %1, %2, %3;" : "=l"(d) : "l"(a), "l"(b), "l"(c));
    return d;
}
__device__ __forceinline__ void upk(unsigned long long v, float& lo, float& hi) {
    asm("mov.b64 {%0,%1}, %2;" : "=f"(lo), "=f"(hi) : "l"(v));
}
__device__ __forceinline__ float tanh_apx(float x) {
    float y;
    asm("tanh.approx.f32 %0, %1;" : "=f"(y) : "f"(x));
    return y;
}
__device__ __forceinline__ float sig_apx(float x) {
    return fmaf(tanh_apx(0.5f * x), 0.5f, 0.5f);   // 1 MUFU
}

__global__ void __launch_bounds__(256, 2)
enc_kernel(const float* __restrict__ x,
           const float* __restrict__ Wih,
           const float* __restrict__ Whh,
           const float* __restrict__ bih,
           const float* __restrict__ bhh)
{
    __shared__ __align__(16) float h_s[65 * BB];     // [k][b]; k=64 row = x_t
    __shared__ float gbuf[BB * GATES];               // gate exchange [b][g]

    const int tid   = threadIdx.x;
    const int bbase = blockIdx.x * BB;
    const int g     = tid;

    // ---- time-invariant weights in registers (65 scalars) ----
    float Wr[65];
#pragma unroll
    for (int k = 0; k < 64; k++) Wr[k] = Whh[g * 64 + k];
    Wr[64] = Wih[g];                       // x contribution (IN = 1)
    const float bias = bih[g] + bhh[g];
    const unsigned long long bias2 = pk2(bias, bias);

    // ---- zero h state ----
    for (int i = tid; i < 65 * BB; i += 256) h_s[i] = 0.0f;

    const int j = tid & 63;      // epilogue cell index
    const int b = tid >> 6;      // epilogue batch row (0..3)
    float c = 0.0f;              // cell state for (j, b)

    // prefetch x for t=0
    float xr = 0.0f;
    if (tid < BB) xr = x[bbase + tid];

    __syncthreads();

    for (int t = 0; t < T_STEPS; t++) {
        if (tid < BB) h_s[64 * BB + tid] = xr;   // stage x_t
        __syncthreads();   // orders prev epilogue h writes + x before reads

        // prefetch next x while the gate loop runs (hides LDG latency)
        if (tid < BB && t + 1 < T_STEPS) xr = x[(t + 1) * BATCH + bbase + tid];

        // ---- gates[b][g] = sum_k h[k][b] * Wr[k], 4 rows as 2 f32x2 pairs
        unsigned long long a0 = bias2, a1 = bias2;
#pragma unroll
        for (int k = 0; k < 65; k++) {
            const ulonglong2 hv = *(const ulonglong2*)(h_s + k * BB); // rows 0..3
            const unsigned long long w2 = pk2(Wr[k], Wr[k]);
            a0 = fma2(hv.x, w2, a0);
            a1 = fma2(hv.y, w2, a1);
        }

        float v0, v1, v2, v3;
        upk(a0, v0, v1); upk(a1, v2, v3);
        gbuf[0 * GATES + g] = v0;
        gbuf[1 * GATES + g] = v1;
        gbuf[2 * GATES + g] = v2;
        gbuf[3 * GATES + g] = v3;
        __syncthreads();

        // ---- LSTM cell epilogue: one (cell, row) per thread, 5 MUFU total
        {
            const float* gb = gbuf + b * GATES;
            const float i_ = sig_apx(gb[j]);
            const float f_ = sig_apx(gb[64 + j]);
            const float G_ = tanh_apx(gb[128 + j]);
            const float o_ = sig_apx(gb[192 + j]);
            c = fmaf(f_, c, i_ * G_);
            h_s[j * BB + b] = o_ * tanh_apx(c);
        }
        // next iteration's top barrier provides the ordering
    }

    __syncthreads();
    // ---- export final h (transposed [k][b]) for the decoder ----
    if (tid < HID * BB) {
        const int k = tid >> 2;
        const int bb = tid & 3;
        g_henc[k * BATCH + bbase + bb] = h_s[k * BB + bb];
    }
}

__global__ void __launch_bounds__(32)
dec_kernel(const float* __restrict__ Wih,
           const float* __restrict__ Whh,
           const float* __restrict__ bih,
           const float* __restrict__ bhh,
           float* __restrict__ out)
{
    const int b = blockIdx.x * 32 + threadIdx.x;

    // z[g] = h_enc[b] . Wih_d[g] + bias  (constant across decoder steps)
    float z0 = bih[0] + bhh[0];
    float z1 = bih[1] + bhh[1];
    float z2 = bih[2] + bhh[2];
    float z3 = bih[3] + bhh[3];
#pragma unroll 8
    for (int k = 0; k < HID; k++) {
        const float hv = g_henc[k * BATCH + b];   // coalesced
        z0 = fmaf(hv, Wih[0 * HID + k], z0);
        z1 = fmaf(hv, Wih[1 * HID + k], z1);
        z2 = fmaf(hv, Wih[2 * HID + k], z2);
        z3 = fmaf(hv, Wih[3 * HID + k], z3);
    }
    const float w0 = Whh[0], w1 = Whh[1], w2 = Whh[2], w3 = Whh[3];

    float h = 0.0f, c = 0.0f;
    for (int t = 0; t < T_STEPS; t++) {
        const float i_ = sig_apx(fmaf(h, w0, z0));
        const float f_ = sig_apx(fmaf(h, w1, z1));
        const float G_ = tanh_apx(fmaf(h, w2, z2));
        const float o_ = sig_apx(fmaf(h, w3, z3));
        c = fmaf(f_, c, i_ * G_);
        h = o_ * tanh_apx(c);
        out[t * BATCH + b] = h;   // coalesced
    }
}

extern "C" void kernel_launch(void* const* d_in, const int* in_sizes, int n_in,
                              void* d_out, int out_size)
{
    const float* x     = (const float*)d_in[0];
    const float* Wih_e = (const float*)d_in[1];
    const float* Whh_e = (const float*)d_in[2];
    const float* bih_e = (const float*)d_in[3];
    const float* bhh_e = (const float*)d_in[4];
    const float* Wih_d = (const float*)d_in[5];
    const float* Whh_d = (const float*)d_in[6];
    const float* bih_d = (const float*)d_in[7];
    const float* bhh_d = (const float*)d_in[8];

    enc_kernel<<<BATCH / BB, 256>>>(x, Wih_e, Whh_e, bih_e, bhh_e);
    dec_kernel<<<BATCH / 32, 32>>>(Wih_d, Whh_d, bih_d, bhh_d, (float*)d_out);
}